// round 4
// baseline (speedup 1.0000x reference)
#include <cuda_runtime.h>

// ---------------- scratch (static device globals; no allocation allowed) ----
#define N_CAP   50176
#define E_CAP   1000448

__device__ float g_agg1[N_CAP * 128];      // layer-1 neighbor mean (25.7 MB)
__device__ float g_agg2[N_CAP * 256];      // layer-2 neighbor mean (51.4 MB)
__device__ float g_h1  [N_CAP * 256];      // layer-1 activations   (51.4 MB)
__device__ int   g_cnt   [N_CAP];          // in-degree
__device__ int   g_off   [N_CAP + 1];      // CSR row offsets
__device__ int   g_cursor[N_CAP];          // scatter cursors
__device__ int   g_srt   [E_CAP];          // CSR column (source node) ids

// ---------------- CSR build --------------------------------------------------
__global__ void zero_i(int* __restrict__ p, int n) {
    int i = blockIdx.x * blockDim.x + threadIdx.x;
    if (i < n) p[i] = 0;
}

__global__ void count_kernel(const int* __restrict__ dst, int E, int N,
                             int* __restrict__ cnt) {
    int i = blockIdx.x * blockDim.x + threadIdx.x;
    if (i >= E) return;
    int d = dst[i];
    d = min(max(d, 0), N - 1);          // defensive clamp (no traps, ever)
    atomicAdd(&cnt[d], 1);
}

// single-block Hillis-Steele scan over cnt -> off (off[i+1] inclusive) + cursor
__global__ void scan_kernel(const int* __restrict__ cnt, int* __restrict__ off,
                            int* __restrict__ cursor, int N) {
    __shared__ int sh[1024];
    __shared__ int carry_s;
    int tid = threadIdx.x;
    if (tid == 0) { carry_s = 0; off[0] = 0; }
    __syncthreads();
    for (int base = 0; base < N; base += 1024) {
        int i = base + tid;
        int v = (i < N) ? cnt[i] : 0;
        sh[tid] = v;
        __syncthreads();
#pragma unroll
        for (int d = 1; d < 1024; d <<= 1) {
            int t = (tid >= d) ? sh[tid - d] : 0;
            __syncthreads();
            sh[tid] += t;
            __syncthreads();
        }
        int incl = sh[tid] + carry_s;
        if (i < N) {
            off[i + 1] = incl;
            cursor[i]  = incl - v;      // exclusive prefix = bucket start
        }
        __syncthreads();
        if (tid == 0) carry_s += sh[1023];
        __syncthreads();
    }
}

__global__ void scatter_kernel(const int* __restrict__ src,
                               const int* __restrict__ dst, int E, int N,
                               int* __restrict__ cursor, int* __restrict__ srt) {
    int i = blockIdx.x * blockDim.x + threadIdx.x;
    if (i >= E) return;
    int d = dst[i];
    int s = src[i];
    d = min(max(d, 0), N - 1);
    s = min(max(s, 0), N - 1);
    int pos = atomicAdd(&cursor[d], 1);
    srt[pos] = s;
}

// ---------------- gather aggregation (mean over in-neighbors) ----------------
// one warp per node; lane l owns float4 chunks l, l+32, ... of the D-float row
template <int VEC>   // VEC = D / 128
__global__ void gather_agg(const float* __restrict__ x,
                           const int* __restrict__ srt,
                           const int* __restrict__ off,
                           float* __restrict__ agg, int N, int D) {
    int warp = (blockIdx.x * blockDim.x + threadIdx.x) >> 5;
    int lane = threadIdx.x & 31;
    if (warp >= N) return;
    int s0 = off[warp], s1 = off[warp + 1];

    float4 acc[VEC];
#pragma unroll
    for (int c = 0; c < VEC; c++) acc[c] = make_float4(0.f, 0.f, 0.f, 0.f);

    int e = s0;
    for (; e + 1 < s1; e += 2) {        // unroll x2 for MLP
        int sA = srt[e], sB = srt[e + 1];
        const float4* rA = reinterpret_cast<const float4*>(x + (size_t)sA * D);
        const float4* rB = reinterpret_cast<const float4*>(x + (size_t)sB * D);
#pragma unroll
        for (int c = 0; c < VEC; c++) {
            float4 a = rA[lane + 32 * c];
            float4 b = rB[lane + 32 * c];
            acc[c].x += a.x + b.x; acc[c].y += a.y + b.y;
            acc[c].z += a.z + b.z; acc[c].w += a.w + b.w;
        }
    }
    if (e < s1) {
        int sA = srt[e];
        const float4* rA = reinterpret_cast<const float4*>(x + (size_t)sA * D);
#pragma unroll
        for (int c = 0; c < VEC; c++) {
            float4 a = rA[lane + 32 * c];
            acc[c].x += a.x; acc[c].y += a.y; acc[c].z += a.z; acc[c].w += a.w;
        }
    }

    float r = (s1 > s0) ? 1.0f / (float)(s1 - s0) : 0.0f;
    float4* o = reinterpret_cast<float4*>(agg + (size_t)warp * D);
#pragma unroll
    for (int c = 0; c < VEC; c++) {
        float4 v = acc[c];
        v.x *= r; v.y *= r; v.z *= r; v.w *= r;
        o[lane + 32 * c] = v;
    }
}

// ---------------- fused dual-GEMM: C = relu(A1 B1^T + A2 B2^T + bias) -------
// A1, A2: [M, D] row-major.  B1, B2: [NO, D] row-major.  C: [M, NO].
__global__ void __launch_bounds__(256, 2)
sage_gemm(const float* __restrict__ A1, const float* __restrict__ A2,
          const float* __restrict__ B1, const float* __restrict__ B2,
          const float* __restrict__ bias, float* __restrict__ C,
          int M, int D, int NO) {
    constexpr int BM = 128, BN = 128, BK = 16, TM = 8, TN = 8;
    __shared__ float As[BK][BM];
    __shared__ float Bs[BK][BN];

    int tid = threadIdx.x;
    int tx = tid & 15;
    int ty = tid >> 4;
    int rowBase = blockIdx.y * BM;
    int colBase = blockIdx.x * BN;

    float acc[TM][TN] = {};

    int ktiles = (2 * D) / BK;
    for (int kt = 0; kt < ktiles; kt++) {
        int kg = kt * BK;
        const float* A = (kg < D) ? A1 : A2;
        const float* B = (kg < D) ? B1 : B2;
        int kb = (kg < D) ? kg : kg - D;

#pragma unroll
        for (int it = 0; it < 2; it++) {
            int f  = tid + it * 256;
            int m  = f >> 2;
            int k4 = (f & 3) * 4;
            float4 v = make_float4(0.f, 0.f, 0.f, 0.f);
            int gm = rowBase + m;
            if (gm < M)
                v = *reinterpret_cast<const float4*>(A + (size_t)gm * D + kb + k4);
            As[k4 + 0][m] = v.x; As[k4 + 1][m] = v.y;
            As[k4 + 2][m] = v.z; As[k4 + 3][m] = v.w;
        }
#pragma unroll
        for (int it = 0; it < 2; it++) {
            int f  = tid + it * 256;
            int n  = f >> 2;
            int k4 = (f & 3) * 4;
            float4 v = make_float4(0.f, 0.f, 0.f, 0.f);
            int gn = colBase + n;
            if (gn < NO)
                v = *reinterpret_cast<const float4*>(B + (size_t)gn * D + kb + k4);
            Bs[k4 + 0][n] = v.x; Bs[k4 + 1][n] = v.y;
            Bs[k4 + 2][n] = v.z; Bs[k4 + 3][n] = v.w;
        }
        __syncthreads();

#pragma unroll
        for (int kk = 0; kk < BK; kk++) {
            float a[TM], b[TN];
#pragma unroll
            for (int i = 0; i < TM; i++) a[i] = As[kk][ty * TM + i];
#pragma unroll
            for (int j = 0; j < TN; j++) b[j] = Bs[kk][tx * TN + j];
#pragma unroll
            for (int i = 0; i < TM; i++)
#pragma unroll
                for (int j = 0; j < TN; j++)
                    acc[i][j] += a[i] * b[j];
        }
        __syncthreads();
    }

#pragma unroll
    for (int i = 0; i < TM; i++) {
        int gm = rowBase + ty * TM + i;
        if (gm >= M) continue;
#pragma unroll
        for (int j = 0; j < TN; j++) {
            int gn = colBase + tx * TN + j;
            if (gn < NO) {
                float v = acc[i][j] + bias[gn];
                C[(size_t)gm * NO + gn] = fmaxf(v, 0.f);
            }
        }
    }
}

// ---------------- launch ------------------------------------------------------
extern "C" void kernel_launch(void* const* d_in, const int* in_sizes, int n_in,
                              void* d_out, int out_size) {
    const float* x   = (const float*)d_in[0];
    const int*   ei  = (const int*)d_in[1];     // int32! (JAX x64 disabled)
    const float* Ws1 = (const float*)d_in[2];
    const float* Wn1 = (const float*)d_in[3];
    const float* b1  = (const float*)d_in[4];
    const float* Ws2 = (const float*)d_in[5];
    const float* Wn2 = (const float*)d_in[6];
    const float* b2  = (const float*)d_in[7];
    float*       out = (float*)d_out;

    const int H     = in_sizes[4];             // 256
    const int F_IN  = in_sizes[2] / H;         // 128
    const int N     = in_sizes[0] / F_IN;      // 50000
    const int E     = in_sizes[1] / 2;         // 800000
    const int F_OUT = in_sizes[7];             // 128

    const int* src = ei;
    const int* dst = ei + E;

    float *agg1, *agg2, *h1;
    int *cnt, *off, *cursor, *srt;
    cudaGetSymbolAddress((void**)&agg1,   g_agg1);
    cudaGetSymbolAddress((void**)&agg2,   g_agg2);
    cudaGetSymbolAddress((void**)&h1,     g_h1);
    cudaGetSymbolAddress((void**)&cnt,    g_cnt);
    cudaGetSymbolAddress((void**)&off,    g_off);
    cudaGetSymbolAddress((void**)&cursor, g_cursor);
    cudaGetSymbolAddress((void**)&srt,    g_srt);

    // 1) CSR build
    zero_i<<<(N + 255) / 256, 256>>>(cnt, N);
    count_kernel<<<(E + 255) / 256, 256>>>(dst, E, N, cnt);
    scan_kernel<<<1, 1024>>>(cnt, off, cursor, N);
    scatter_kernel<<<(E + 255) / 256, 256>>>(src, dst, E, N, cursor, srt);

    // 2) layer-1 aggregation (gather) -> agg1 [N, F_IN]
    gather_agg<1><<<(N * 32 + 255) / 256, 256>>>(x, srt, off, agg1, N, F_IN);

    // 3) layer-1 GEMM: h1 = relu(x Ws1^T + agg1 Wn1^T + b1)   [N, H]
    {
        dim3 grid((H + 127) / 128, (N + 127) / 128);
        sage_gemm<<<grid, 256>>>(x, agg1, Ws1, Wn1, b1, h1, N, F_IN, H);
    }

    // 4) layer-2 aggregation (gather) -> agg2 [N, H]
    gather_agg<2><<<(N * 32 + 255) / 256, 256>>>(h1, srt, off, agg2, N, H);

    // 5) layer-2 GEMM: out = relu(h1 Ws2^T + agg2 Wn2^T + b2)  [N, F_OUT]
    {
        dim3 grid((F_OUT + 127) / 128, (N + 127) / 128);
        sage_gemm<<<grid, 256>>>(h1, agg2, Ws2, Wn2, b2, out, N, H, F_OUT);
    }
}

// round 6
// speedup vs baseline: 1.2393x; 1.2393x over previous
#include <cuda_runtime.h>
#include <cuda_bf16.h>
#include <cstdint>

// ---------------- scratch (static device globals; no allocation allowed) ----
#define N_CAP   50176
#define E_CAP   1000448

__device__ float    g_h1   [N_CAP * 256];          // layer-1 activations fp32
__device__ uint16_t g_x_hi [N_CAP * 128];
__device__ uint16_t g_x_lo [N_CAP * 128];
__device__ uint16_t g_a1_hi[N_CAP * 128];
__device__ uint16_t g_a1_lo[N_CAP * 128];
__device__ uint16_t g_h1_hi[N_CAP * 256];
__device__ uint16_t g_h1_lo[N_CAP * 256];
__device__ uint16_t g_a2_hi[N_CAP * 256];
__device__ uint16_t g_a2_lo[N_CAP * 256];
__device__ uint16_t g_w_hi [4 * 32768];            // Ws1,Wn1,Ws2,Wn2
__device__ uint16_t g_w_lo [4 * 32768];
__device__ int      g_cnt   [N_CAP];
__device__ int      g_off   [N_CAP + 1];
__device__ int      g_cursor[N_CAP];
__device__ int      g_srt   [E_CAP];

// ---------------- small helpers ----------------------------------------------
__device__ __forceinline__ uint32_t smem_u32(const void* p) {
    uint32_t a;
    asm("{ .reg .u64 t; cvta.to.shared.u64 t, %1; cvt.u32.u64 %0, t; }"
        : "=r"(a) : "l"(p));
    return a;
}
__device__ __forceinline__ void hilo(float v, uint16_t& h, uint16_t& l) {
    __nv_bfloat16 hb = __float2bfloat16(v);
    __nv_bfloat16 lb = __float2bfloat16(v - __bfloat162float(hb));
    h = __bfloat16_as_ushort(hb);
    l = __bfloat16_as_ushort(lb);
}
__device__ __forceinline__ void ldsm_x4(uint32_t* r, uint32_t addr) {
    asm volatile("ldmatrix.sync.aligned.m8n8.x4.shared.b16 {%0,%1,%2,%3}, [%4];"
                 : "=r"(r[0]), "=r"(r[1]), "=r"(r[2]), "=r"(r[3]) : "r"(addr));
}
__device__ __forceinline__ void ldsm_x2(uint32_t* r, uint32_t addr) {
    asm volatile("ldmatrix.sync.aligned.m8n8.x2.shared.b16 {%0,%1}, [%2];"
                 : "=r"(r[0]), "=r"(r[1]) : "r"(addr));
}
__device__ __forceinline__ void mma_bf16(float* d, const uint32_t* a,
                                         const uint32_t* b) {
    asm volatile(
        "mma.sync.aligned.m16n8k16.row.col.f32.bf16.bf16.f32 "
        "{%0,%1,%2,%3}, {%4,%5,%6,%7}, {%8,%9}, {%0,%1,%2,%3};"
        : "+f"(d[0]), "+f"(d[1]), "+f"(d[2]), "+f"(d[3])
        : "r"(a[0]), "r"(a[1]), "r"(a[2]), "r"(a[3]), "r"(b[0]), "r"(b[1]));
}

// ---------------- CSR build ---------------------------------------------------
__global__ void zero_i(int* __restrict__ p, int n) {
    int i = blockIdx.x * blockDim.x + threadIdx.x;
    if (i < n) p[i] = 0;
}

__global__ void count_kernel(const int* __restrict__ dst, int E, int N,
                             int* __restrict__ cnt) {
    int i = blockIdx.x * blockDim.x + threadIdx.x;
    if (i >= E) return;
    int d = min(max(dst[i], 0), N - 1);
    atomicAdd(&cnt[d], 1);
}

__global__ void scan_kernel(const int* __restrict__ cnt, int* __restrict__ off,
                            int* __restrict__ cursor, int N) {
    __shared__ int sh[1024];
    __shared__ int carry_s;
    int tid = threadIdx.x;
    if (tid == 0) { carry_s = 0; off[0] = 0; }
    __syncthreads();
    for (int base = 0; base < N; base += 1024) {
        int i = base + tid;
        int v = (i < N) ? cnt[i] : 0;
        sh[tid] = v;
        __syncthreads();
#pragma unroll
        for (int d = 1; d < 1024; d <<= 1) {
            int t = (tid >= d) ? sh[tid - d] : 0;
            __syncthreads();
            sh[tid] += t;
            __syncthreads();
        }
        int incl = sh[tid] + carry_s;
        if (i < N) {
            off[i + 1] = incl;
            cursor[i]  = incl - v;
        }
        __syncthreads();
        if (tid == 0) carry_s += sh[1023];
        __syncthreads();
    }
}

__global__ void scatter_kernel(const int* __restrict__ src,
                               const int* __restrict__ dst, int E, int N,
                               int* __restrict__ cursor, int* __restrict__ srt) {
    int i = blockIdx.x * blockDim.x + threadIdx.x;
    if (i >= E) return;
    int d = min(max(dst[i], 0), N - 1);
    int s = min(max(src[i], 0), N - 1);
    int pos = atomicAdd(&cursor[d], 1);
    srt[pos] = s;
}

// ---------------- fp32 -> bf16 hi/lo conversion -------------------------------
__global__ void conv_hilo(const float* __restrict__ s, uint16_t* __restrict__ hi,
                          uint16_t* __restrict__ lo, int n) {
    int i = blockIdx.x * blockDim.x + threadIdx.x;
    if (i < n) hilo(s[i], hi[i], lo[i]);
}

// ---------------- gather aggregation -> bf16 hi/lo ----------------------------
template <int VEC>   // VEC = D / 128
__global__ void gather_agg_bf16(const float* __restrict__ x,
                                const int* __restrict__ srt,
                                const int* __restrict__ off,
                                uint16_t* __restrict__ hi,
                                uint16_t* __restrict__ lo, int N, int D) {
    int warp = (blockIdx.x * blockDim.x + threadIdx.x) >> 5;
    int lane = threadIdx.x & 31;
    if (warp >= N) return;
    int s0 = off[warp], s1 = off[warp + 1];

    float4 acc[VEC];
#pragma unroll
    for (int c = 0; c < VEC; c++) acc[c] = make_float4(0.f, 0.f, 0.f, 0.f);

    int e = s0;
    for (; e + 1 < s1; e += 2) {
        int sA = srt[e], sB = srt[e + 1];
        const float4* rA = reinterpret_cast<const float4*>(x + (size_t)sA * D);
        const float4* rB = reinterpret_cast<const float4*>(x + (size_t)sB * D);
#pragma unroll
        for (int c = 0; c < VEC; c++) {
            float4 a = rA[lane + 32 * c];
            float4 b = rB[lane + 32 * c];
            acc[c].x += a.x + b.x; acc[c].y += a.y + b.y;
            acc[c].z += a.z + b.z; acc[c].w += a.w + b.w;
        }
    }
    if (e < s1) {
        int sA = srt[e];
        const float4* rA = reinterpret_cast<const float4*>(x + (size_t)sA * D);
#pragma unroll
        for (int c = 0; c < VEC; c++) {
            float4 a = rA[lane + 32 * c];
            acc[c].x += a.x; acc[c].y += a.y; acc[c].z += a.z; acc[c].w += a.w;
        }
    }

    float r = (s1 > s0) ? 1.0f / (float)(s1 - s0) : 0.0f;
#pragma unroll
    for (int c = 0; c < VEC; c++) {
        float4 v = acc[c];
        v.x *= r; v.y *= r; v.z *= r; v.w *= r;
        uint16_t h0, l0, h1v, l1, h2, l2, h3, l3;
        hilo(v.x, h0, l0); hilo(v.y, h1v, l1);
        hilo(v.z, h2, l2); hilo(v.w, h3, l3);
        size_t base = (size_t)warp * D + (lane + 32 * c) * 4;
        uint2 hp = make_uint2((uint32_t)h0 | ((uint32_t)h1v << 16),
                              (uint32_t)h2 | ((uint32_t)h3 << 16));
        uint2 lp = make_uint2((uint32_t)l0 | ((uint32_t)l1 << 16),
                              (uint32_t)l2 | ((uint32_t)l3 << 16));
        *reinterpret_cast<uint2*>(hi + base) = hp;
        *reinterpret_cast<uint2*>(lo + base) = lp;
    }
}

// ---------------- bf16x3 segmented GEMM (mma.sync HMMA) -----------------------
// C[M, LDC] tile (128x128 per CTA) = relu( sum_seg A_seg B_seg^T + bias )
// Segments: 6 x (M x D) A operands paired with 6 x (LDC x D) B operands.
struct SegPtrs {
    const uint16_t* a[6];
    const uint16_t* b[6];
};

template <int LDC, bool WRITE_HILO>
__global__ void __launch_bounds__(256)
gemm_bf16x3(SegPtrs segs, int D, int M, const float* __restrict__ bias,
            float* __restrict__ C, uint16_t* __restrict__ Chi,
            uint16_t* __restrict__ Clo) {
    __shared__ uint16_t As[128 * 40];   // 32 k + 8 pad per row
    __shared__ uint16_t Bs[128 * 40];

    int tid = threadIdx.x;
    int wid = tid >> 5;
    int lane = tid & 31;
    int rowBase = blockIdx.y * 128;
    int colBase = blockIdx.x * 128;
    int warp_m = (wid & 3) * 32;        // 4 warps over M
    int warp_n = (wid >> 2) * 64;       // 2 warps over N

    float acc[2][8][4] = {};

    uint32_t as_b = smem_u32(As), bs_b = smem_u32(Bs);
    int nIters = (6 * D) / 32;
    for (int it = 0; it < nIters; it++) {
        int seg = (it * 32) / D;
        int kin = (it * 32) % D;
        const uint16_t* Ag = segs.a[seg];
        const uint16_t* Bg = segs.b[seg];

#pragma unroll
        for (int h = 0; h < 2; h++) {
            int f  = tid + h * 256;
            int r  = f >> 2;
            int kc = (f & 3) * 8;
            int gm = rowBase + r;
            uint4 va = make_uint4(0, 0, 0, 0);
            if (gm < M)
                va = *reinterpret_cast<const uint4*>(Ag + (size_t)gm * D + kin + kc);
            *reinterpret_cast<uint4*>(As + r * 40 + kc) = va;
            uint4 vb = *reinterpret_cast<const uint4*>(
                Bg + (size_t)(colBase + r) * D + kin + kc);
            *reinterpret_cast<uint4*>(Bs + r * 40 + kc) = vb;
        }
        __syncthreads();

#pragma unroll
        for (int ks = 0; ks < 32; ks += 16) {
            uint32_t bfr[8][2];
#pragma unroll
            for (int nt = 0; nt < 8; nt++) {
                uint32_t addr = bs_b +
                    ((warp_n + nt * 8 + (lane & 7)) * 40 + ks +
                     ((lane >> 3) & 1) * 8) * 2;
                ldsm_x2(bfr[nt], addr);
            }
#pragma unroll
            for (int mt = 0; mt < 2; mt++) {
                uint32_t afr[4];
                uint32_t addr = as_b +
                    ((warp_m + mt * 16 + (lane & 15)) * 40 + ks +
                     (lane >> 4) * 8) * 2;
                ldsm_x4(afr, addr);
#pragma unroll
                for (int nt = 0; nt < 8; nt++)
                    mma_bf16(acc[mt][nt], afr, bfr[nt]);
            }
        }
        __syncthreads();
    }

    // epilogue: bias + relu (+ optional hi/lo bf16 output)
#pragma unroll
    for (int mt = 0; mt < 2; mt++) {
        int gm0 = rowBase + warp_m + mt * 16 + (lane >> 2);
#pragma unroll
        for (int nt = 0; nt < 8; nt++) {
            int n = colBase + warp_n + nt * 8 + (lane & 3) * 2;
            float b0 = bias[n], b1 = bias[n + 1];
#pragma unroll
            for (int half = 0; half < 2; half++) {
                int gm = gm0 + half * 8;
                if (gm >= M) continue;
                float v0 = fmaxf(acc[mt][nt][half * 2 + 0] + b0, 0.f);
                float v1 = fmaxf(acc[mt][nt][half * 2 + 1] + b1, 0.f);
                *reinterpret_cast<float2*>(C + (size_t)gm * LDC + n) =
                    make_float2(v0, v1);
                if (WRITE_HILO) {
                    uint16_t h0, l0, h1v, l1;
                    hilo(v0, h0, l0); hilo(v1, h1v, l1);
                    *reinterpret_cast<uint32_t*>(Chi + (size_t)gm * LDC + n) =
                        (uint32_t)h0 | ((uint32_t)h1v << 16);
                    *reinterpret_cast<uint32_t*>(Clo + (size_t)gm * LDC + n) =
                        (uint32_t)l0 | ((uint32_t)l1 << 16);
                }
            }
        }
    }
}

// ---------------- launch -------------------------------------------------------
extern "C" void kernel_launch(void* const* d_in, const int* in_sizes, int n_in,
                              void* d_out, int out_size) {
    const float* x   = (const float*)d_in[0];
    const int*   ei  = (const int*)d_in[1];
    const float* Ws1 = (const float*)d_in[2];
    const float* Wn1 = (const float*)d_in[3];
    const float* b1  = (const float*)d_in[4];
    const float* Ws2 = (const float*)d_in[5];
    const float* Wn2 = (const float*)d_in[6];
    const float* b2  = (const float*)d_in[7];
    float*       out = (float*)d_out;

    const int H     = in_sizes[4];             // 256
    const int F_IN  = in_sizes[2] / H;         // 128
    const int N     = in_sizes[0] / F_IN;      // 50000
    const int E     = in_sizes[1] / 2;         // 800000
    const int F_OUT = in_sizes[7];             // 128

    const int* src = ei;
    const int* dst = ei + E;

    float* h1;
    uint16_t *x_hi, *x_lo, *a1_hi, *a1_lo, *h1_hi, *h1_lo, *a2_hi, *a2_lo;
    uint16_t *w_hi, *w_lo;
    int *cnt, *off, *cursor, *srt;
    cudaGetSymbolAddress((void**)&h1,    g_h1);
    cudaGetSymbolAddress((void**)&x_hi,  g_x_hi);
    cudaGetSymbolAddress((void**)&x_lo,  g_x_lo);
    cudaGetSymbolAddress((void**)&a1_hi, g_a1_hi);
    cudaGetSymbolAddress((void**)&a1_lo, g_a1_lo);
    cudaGetSymbolAddress((void**)&h1_hi, g_h1_hi);
    cudaGetSymbolAddress((void**)&h1_lo, g_h1_lo);
    cudaGetSymbolAddress((void**)&a2_hi, g_a2_hi);
    cudaGetSymbolAddress((void**)&a2_lo, g_a2_lo);
    cudaGetSymbolAddress((void**)&w_hi,  g_w_hi);
    cudaGetSymbolAddress((void**)&w_lo,  g_w_lo);
    cudaGetSymbolAddress((void**)&cnt,    g_cnt);
    cudaGetSymbolAddress((void**)&off,    g_off);
    cudaGetSymbolAddress((void**)&cursor, g_cursor);
    cudaGetSymbolAddress((void**)&srt,    g_srt);

    // 1) CSR build
    zero_i<<<(N + 255) / 256, 256>>>(cnt, N);
    count_kernel<<<(E + 255) / 256, 256>>>(dst, E, N, cnt);
    scan_kernel<<<1, 1024>>>(cnt, off, cursor, N);
    scatter_kernel<<<(E + 255) / 256, 256>>>(src, dst, E, N, cursor, srt);

    // 2) hi/lo conversions: x and all 4 weight matrices
    conv_hilo<<<(N * F_IN + 255) / 256, 256>>>(x, x_hi, x_lo, N * F_IN);
    conv_hilo<<<128, 256>>>(Ws1, w_hi + 0,      w_lo + 0,      H * F_IN);
    conv_hilo<<<128, 256>>>(Wn1, w_hi + 32768,  w_lo + 32768,  H * F_IN);
    conv_hilo<<<128, 256>>>(Ws2, w_hi + 65536,  w_lo + 65536,  F_OUT * H);
    conv_hilo<<<128, 256>>>(Wn2, w_hi + 98304,  w_lo + 98304,  F_OUT * H);

    // 3) layer-1 aggregation -> agg1 hi/lo (bf16)
    gather_agg_bf16<1><<<(N * 32 + 255) / 256, 256>>>(x, srt, off, a1_hi, a1_lo,
                                                      N, F_IN);

    // 4) layer-1 GEMM: h1 = relu(x Ws1^T + agg1 Wn1^T + b1), K = 6*128
    {
        SegPtrs s;
        s.a[0] = x_hi;  s.a[1] = x_hi;  s.a[2] = x_lo;
        s.a[3] = a1_hi; s.a[4] = a1_hi; s.a[5] = a1_lo;
        s.b[0] = w_hi + 0;     s.b[1] = w_lo + 0;     s.b[2] = w_hi + 0;
        s.b[3] = w_hi + 32768; s.b[4] = w_lo + 32768; s.b[5] = w_hi + 32768;
        dim3 grid(H / 128, (N + 127) / 128);
        gemm_bf16x3<256, true><<<grid, 256>>>(s, F_IN, N, b1, h1, h1_hi, h1_lo);
    }

    // 5) layer-2 aggregation (reads fp32 h1) -> agg2 hi/lo
    gather_agg_bf16<2><<<(N * 32 + 255) / 256, 256>>>(h1, srt, off, a2_hi, a2_lo,
                                                      N, H);

    // 6) layer-2 GEMM: out = relu(h1 Ws2^T + agg2 Wn2^T + b2), K = 6*256
    {
        SegPtrs s;
        s.a[0] = h1_hi; s.a[1] = h1_hi; s.a[2] = h1_lo;
        s.a[3] = a2_hi; s.a[4] = a2_hi; s.a[5] = a2_lo;
        s.b[0] = w_hi + 65536; s.b[1] = w_lo + 65536; s.b[2] = w_hi + 65536;
        s.b[3] = w_hi + 98304; s.b[4] = w_lo + 98304; s.b[5] = w_hi + 98304;
        dim3 grid(F_OUT / 128, (N + 127) / 128);
        gemm_bf16x3<128, false><<<grid, 256>>>(s, H, N, b2, out, nullptr,
                                               nullptr);
    }
}

// round 7
// speedup vs baseline: 2.2017x; 1.7765x over previous
#include <cuda_runtime.h>
#include <cuda_bf16.h>
#include <cstdint>

// ---------------- scratch (static device globals; no allocation allowed) ----
#define N_CAP   50176
#define E_CAP   1000448
#define MAXBLK  64

__device__ uint16_t g_x_hi [N_CAP * 128];
__device__ uint16_t g_x_lo [N_CAP * 128];
__device__ uint16_t g_a1_hi[N_CAP * 128];
__device__ uint16_t g_a1_lo[N_CAP * 128];
__device__ uint16_t g_h1_hi[N_CAP * 256];
__device__ uint16_t g_h1_lo[N_CAP * 256];
__device__ float    g_s2z2 [N_CAP * 256];   // [s2 | z2] fp32
__device__ float    g_aggz [N_CAP * 128];   // agg(z2) fp32
__device__ uint16_t g_w_hi [131072];        // Ws1 | Wn1 | w2cat(256x256)
__device__ uint16_t g_w_lo [131072];
__device__ int      g_cnt   [N_CAP];
__device__ int      g_off   [N_CAP + 1];
__device__ int      g_cursor[N_CAP];
__device__ int      g_srt   [E_CAP];
__device__ int      g_bsum  [MAXBLK];
__device__ int      g_bpre  [MAXBLK];

// ---------------- small helpers ----------------------------------------------
__device__ __forceinline__ uint32_t smem_u32(const void* p) {
    uint32_t a;
    asm("{ .reg .u64 t; cvta.to.shared.u64 t, %1; cvt.u32.u64 %0, t; }"
        : "=r"(a) : "l"(p));
    return a;
}
__device__ __forceinline__ void hilo(float v, uint16_t& h, uint16_t& l) {
    __nv_bfloat16 hb = __float2bfloat16(v);
    __nv_bfloat16 lb = __float2bfloat16(v - __bfloat162float(hb));
    h = __bfloat16_as_ushort(hb);
    l = __bfloat16_as_ushort(lb);
}
__device__ __forceinline__ void ldsm_x4(uint32_t* r, uint32_t addr) {
    asm volatile("ldmatrix.sync.aligned.m8n8.x4.shared.b16 {%0,%1,%2,%3}, [%4];"
                 : "=r"(r[0]), "=r"(r[1]), "=r"(r[2]), "=r"(r[3]) : "r"(addr));
}
__device__ __forceinline__ void ldsm_x2(uint32_t* r, uint32_t addr) {
    asm volatile("ldmatrix.sync.aligned.m8n8.x2.shared.b16 {%0,%1}, [%2];"
                 : "=r"(r[0]), "=r"(r[1]) : "r"(addr));
}
__device__ __forceinline__ void mma_bf16(float* d, const uint32_t* a,
                                         const uint32_t* b) {
    asm volatile(
        "mma.sync.aligned.m16n8k16.row.col.f32.bf16.bf16.f32 "
        "{%0,%1,%2,%3}, {%4,%5,%6,%7}, {%8,%9}, {%0,%1,%2,%3};"
        : "+f"(d[0]), "+f"(d[1]), "+f"(d[2]), "+f"(d[3])
        : "r"(a[0]), "r"(a[1]), "r"(a[2]), "r"(a[3]), "r"(b[0]), "r"(b[1]));
}

// ---------------- CSR build ---------------------------------------------------
__global__ void zero_i(int* __restrict__ p, int n) {
    int i = blockIdx.x * blockDim.x + threadIdx.x;
    if (i < n) p[i] = 0;
}

__global__ void count_kernel(const int* __restrict__ dst, int E, int N,
                             int* __restrict__ cnt) {
    int i = blockIdx.x * blockDim.x + threadIdx.x;
    if (i >= E) return;
    int d = min(max(dst[i], 0), N - 1);
    atomicAdd(&cnt[d], 1);
}

// phase 1: per-block sums of 1024-elem chunks
__global__ void block_sum(const int* __restrict__ cnt, int N,
                          int* __restrict__ bsum) {
    __shared__ int sh[1024];
    int i = blockIdx.x * 1024 + threadIdx.x;
    sh[threadIdx.x] = (i < N) ? cnt[i] : 0;
    __syncthreads();
    for (int d = 512; d > 0; d >>= 1) {
        if (threadIdx.x < d) sh[threadIdx.x] += sh[threadIdx.x + d];
        __syncthreads();
    }
    if (threadIdx.x == 0) bsum[blockIdx.x] = sh[0];
}

// phase 2: serial exclusive scan of block sums (tiny)
__global__ void scan_sums(const int* __restrict__ bsum, int* __restrict__ bpre,
                          int nb) {
    if (threadIdx.x == 0) {
        int acc = 0;
        for (int i = 0; i < nb; i++) { bpre[i] = acc; acc += bsum[i]; }
    }
}

// phase 3: per-block Hillis-Steele with carried offset
__global__ void block_scan(const int* __restrict__ cnt, const int* __restrict__ bpre,
                           int* __restrict__ off, int* __restrict__ cursor, int N) {
    __shared__ int sh[1024];
    int tid = threadIdx.x;
    int i = blockIdx.x * 1024 + tid;
    int v = (i < N) ? cnt[i] : 0;
    sh[tid] = v;
    __syncthreads();
#pragma unroll
    for (int d = 1; d < 1024; d <<= 1) {
        int t = (tid >= d) ? sh[tid - d] : 0;
        __syncthreads();
        sh[tid] += t;
        __syncthreads();
    }
    int incl = sh[tid] + bpre[blockIdx.x];
    if (i < N) {
        off[i + 1] = incl;
        cursor[i]  = incl - v;
    }
    if (blockIdx.x == 0 && tid == 0) off[0] = 0;
}

__global__ void scatter_kernel(const int* __restrict__ src,
                               const int* __restrict__ dst, int E, int N,
                               int* __restrict__ cursor, int* __restrict__ srt) {
    int i = blockIdx.x * blockDim.x + threadIdx.x;
    if (i >= E) return;
    int d = min(max(dst[i], 0), N - 1);
    int s = min(max(src[i], 0), N - 1);
    int pos = atomicAdd(&cursor[d], 1);
    srt[pos] = s;
}

// ---------------- fp32 -> bf16 hi/lo conversion -------------------------------
__global__ void conv_hilo(const float* __restrict__ s, uint16_t* __restrict__ hi,
                          uint16_t* __restrict__ lo, int n) {
    int i = blockIdx.x * blockDim.x + threadIdx.x;
    if (i < n) hilo(s[i], hi[i], lo[i]);
}

// ---------------- gather aggregation (D = 128) ---------------------------------
// one warp per node; lane owns one float4 chunk of the 128-float row.
// BF16OUT: write hi/lo bf16; else write fp32 dense (ld 128).
template <bool BF16OUT>
__global__ void gather128(const float* __restrict__ x, int ldin, int coloff,
                          const int* __restrict__ srt,
                          const int* __restrict__ off,
                          uint16_t* __restrict__ hi, uint16_t* __restrict__ lo,
                          float* __restrict__ fout, int N) {
    int warp = (blockIdx.x * blockDim.x + threadIdx.x) >> 5;
    int lane = threadIdx.x & 31;
    if (warp >= N) return;
    int s0 = off[warp], s1 = off[warp + 1];

    float4 acc = make_float4(0.f, 0.f, 0.f, 0.f);
    int e = s0;
    for (; e + 1 < s1; e += 2) {
        int sA = srt[e], sB = srt[e + 1];
        float4 a = *reinterpret_cast<const float4*>(
            x + (size_t)sA * ldin + coloff + lane * 4);
        float4 b = *reinterpret_cast<const float4*>(
            x + (size_t)sB * ldin + coloff + lane * 4);
        acc.x += a.x + b.x; acc.y += a.y + b.y;
        acc.z += a.z + b.z; acc.w += a.w + b.w;
    }
    if (e < s1) {
        int sA = srt[e];
        float4 a = *reinterpret_cast<const float4*>(
            x + (size_t)sA * ldin + coloff + lane * 4);
        acc.x += a.x; acc.y += a.y; acc.z += a.z; acc.w += a.w;
    }

    float r = (s1 > s0) ? 1.0f / (float)(s1 - s0) : 0.0f;
    acc.x *= r; acc.y *= r; acc.z *= r; acc.w *= r;

    if (BF16OUT) {
        uint16_t h0, l0, h1v, l1, h2, l2, h3, l3;
        hilo(acc.x, h0, l0); hilo(acc.y, h1v, l1);
        hilo(acc.z, h2, l2); hilo(acc.w, h3, l3);
        size_t base = (size_t)warp * 128 + lane * 4;
        *reinterpret_cast<uint2*>(hi + base) =
            make_uint2((uint32_t)h0 | ((uint32_t)h1v << 16),
                       (uint32_t)h2 | ((uint32_t)h3 << 16));
        *reinterpret_cast<uint2*>(lo + base) =
            make_uint2((uint32_t)l0 | ((uint32_t)l1 << 16),
                       (uint32_t)l2 | ((uint32_t)l3 << 16));
    } else {
        *reinterpret_cast<float4*>(fout + (size_t)warp * 128 + lane * 4) = acc;
    }
}

// ---------------- bf16x3 GEMM (mma.sync), hi/lo loaded once -------------------
// C128x128 tile per CTA; acc += A_hi B_hi + A_hi B_lo + A_lo B_hi per K-chunk.
struct Seg { const uint16_t *ahi, *alo, *bhi, *blo; };

template <int NSEG, int SEGD, int OUTMODE>   // OUTMODE 0: raw fp32; 1: bias+relu -> hilo
__global__ void __launch_bounds__(256)
gemm3(Seg s0, Seg s1, int M, const float* __restrict__ bias,
      float* __restrict__ C, uint16_t* __restrict__ Chi,
      uint16_t* __restrict__ Clo, int ldc) {
    __shared__ uint16_t AsH[128 * 40], AsL[128 * 40];
    __shared__ uint16_t BsH[128 * 40], BsL[128 * 40];

    int tid = threadIdx.x;
    int wid = tid >> 5;
    int lane = tid & 31;
    int rowBase = blockIdx.y * 128;
    int colBase = blockIdx.x * 128;
    int warp_m = (wid & 3) * 32;
    int warp_n = (wid >> 2) * 64;

    float acc[2][8][4] = {};

    uint32_t asH = smem_u32(AsH), asL = smem_u32(AsL);
    uint32_t bsH = smem_u32(BsH), bsL = smem_u32(BsL);

    constexpr int ITER_PER_SEG = SEGD / 32;
    constexpr int NITER = NSEG * ITER_PER_SEG;
    for (int it = 0; it < NITER; it++) {
        Seg sg = (NSEG == 1 || it < ITER_PER_SEG) ? s0 : s1;
        int kin = (it % ITER_PER_SEG) * 32;

        // load 4 tiles (128 x 32 bf16 each); 2 uint4 per thread per tile
#pragma unroll
        for (int h = 0; h < 2; h++) {
            int f  = tid + h * 256;
            int r  = f >> 2;
            int c8 = (f & 3) * 8;
            int gm = rowBase + r;
            uint4 vah = make_uint4(0, 0, 0, 0), val = make_uint4(0, 0, 0, 0);
            if (gm < M) {
                size_t ao = (size_t)gm * SEGD + kin + c8;
                vah = *reinterpret_cast<const uint4*>(sg.ahi + ao);
                val = *reinterpret_cast<const uint4*>(sg.alo + ao);
            }
            *reinterpret_cast<uint4*>(AsH + r * 40 + c8) = vah;
            *reinterpret_cast<uint4*>(AsL + r * 40 + c8) = val;
            size_t bo = (size_t)(colBase + r) * SEGD + kin + c8;
            *reinterpret_cast<uint4*>(BsH + r * 40 + c8) =
                *reinterpret_cast<const uint4*>(sg.bhi + bo);
            *reinterpret_cast<uint4*>(BsL + r * 40 + c8) =
                *reinterpret_cast<const uint4*>(sg.blo + bo);
        }
        __syncthreads();

#pragma unroll
        for (int ks = 0; ks < 32; ks += 16) {
            uint32_t bH[8][2], bL[8][2];
#pragma unroll
            for (int nt = 0; nt < 8; nt++) {
                uint32_t roff = ((warp_n + nt * 8 + (lane & 7)) * 40 + ks +
                                 ((lane >> 3) & 1) * 8) * 2;
                ldsm_x2(bH[nt], bsH + roff);
                ldsm_x2(bL[nt], bsL + roff);
            }
#pragma unroll
            for (int mt = 0; mt < 2; mt++) {
                uint32_t aH[4], aL[4];
                uint32_t roff = ((warp_m + mt * 16 + (lane & 15)) * 40 + ks +
                                 (lane >> 4) * 8) * 2;
                ldsm_x4(aH, asH + roff);
                ldsm_x4(aL, asL + roff);
#pragma unroll
                for (int nt = 0; nt < 8; nt++) {
                    mma_bf16(acc[mt][nt], aH, bH[nt]);
                    mma_bf16(acc[mt][nt], aH, bL[nt]);
                    mma_bf16(acc[mt][nt], aL, bH[nt]);
                }
            }
        }
        __syncthreads();
    }

    // epilogue
#pragma unroll
    for (int mt = 0; mt < 2; mt++) {
        int gm0 = rowBase + warp_m + mt * 16 + (lane >> 2);
#pragma unroll
        for (int nt = 0; nt < 8; nt++) {
            int n = colBase + warp_n + nt * 8 + (lane & 3) * 2;
#pragma unroll
            for (int half = 0; half < 2; half++) {
                int gm = gm0 + half * 8;
                if (gm >= M) continue;
                float v0 = acc[mt][nt][half * 2 + 0];
                float v1 = acc[mt][nt][half * 2 + 1];
                if (OUTMODE == 1) {
                    v0 = fmaxf(v0 + bias[n], 0.f);
                    v1 = fmaxf(v1 + bias[n + 1], 0.f);
                    uint16_t h0, l0, h1v, l1;
                    hilo(v0, h0, l0); hilo(v1, h1v, l1);
                    *reinterpret_cast<uint32_t*>(Chi + (size_t)gm * ldc + n) =
                        (uint32_t)h0 | ((uint32_t)h1v << 16);
                    *reinterpret_cast<uint32_t*>(Clo + (size_t)gm * ldc + n) =
                        (uint32_t)l0 | ((uint32_t)l1 << 16);
                } else {
                    *reinterpret_cast<float2*>(C + (size_t)gm * ldc + n) =
                        make_float2(v0, v1);
                }
            }
        }
    }
}

// ---------------- final: out = relu(s2 + agg(z2) + b2) -------------------------
__global__ void add_relu(const float* __restrict__ s2z2,
                         const float* __restrict__ aggz,
                         const float* __restrict__ bias,
                         float* __restrict__ out, int N) {
    int i = blockIdx.x * blockDim.x + threadIdx.x;   // float4 index
    if (i >= N * 32) return;
    int row  = i >> 5;
    int col4 = (i & 31) * 4;
    float4 s = *reinterpret_cast<const float4*>(s2z2 + (size_t)row * 256 + col4);
    float4 a = *reinterpret_cast<const float4*>(aggz + (size_t)row * 128 + col4);
    float4 b = *reinterpret_cast<const float4*>(bias + col4);
    float4 o;
    o.x = fmaxf(s.x + a.x + b.x, 0.f);
    o.y = fmaxf(s.y + a.y + b.y, 0.f);
    o.z = fmaxf(s.z + a.z + b.z, 0.f);
    o.w = fmaxf(s.w + a.w + b.w, 0.f);
    *reinterpret_cast<float4*>(out + (size_t)row * 128 + col4) = o;
}

// ---------------- launch -------------------------------------------------------
extern "C" void kernel_launch(void* const* d_in, const int* in_sizes, int n_in,
                              void* d_out, int out_size) {
    const float* x   = (const float*)d_in[0];
    const int*   ei  = (const int*)d_in[1];
    const float* Ws1 = (const float*)d_in[2];
    const float* Wn1 = (const float*)d_in[3];
    const float* b1  = (const float*)d_in[4];
    const float* Ws2 = (const float*)d_in[5];
    const float* Wn2 = (const float*)d_in[6];
    const float* b2  = (const float*)d_in[7];
    float*       out = (float*)d_out;

    const int H     = in_sizes[4];             // 256
    const int F_IN  = in_sizes[2] / H;         // 128
    const int N     = in_sizes[0] / F_IN;      // 50000
    const int E     = in_sizes[1] / 2;         // 800000
    const int F_OUT = in_sizes[7];             // 128

    const int* src = ei;
    const int* dst = ei + E;

    uint16_t *x_hi, *x_lo, *a1_hi, *a1_lo, *h1_hi, *h1_lo, *w_hi, *w_lo;
    float *s2z2, *aggz;
    int *cnt, *off, *cursor, *srt, *bsum, *bpre;
    cudaGetSymbolAddress((void**)&x_hi,  g_x_hi);
    cudaGetSymbolAddress((void**)&x_lo,  g_x_lo);
    cudaGetSymbolAddress((void**)&a1_hi, g_a1_hi);
    cudaGetSymbolAddress((void**)&a1_lo, g_a1_lo);
    cudaGetSymbolAddress((void**)&h1_hi, g_h1_hi);
    cudaGetSymbolAddress((void**)&h1_lo, g_h1_lo);
    cudaGetSymbolAddress((void**)&w_hi,  g_w_hi);
    cudaGetSymbolAddress((void**)&w_lo,  g_w_lo);
    cudaGetSymbolAddress((void**)&s2z2,  g_s2z2);
    cudaGetSymbolAddress((void**)&aggz,  g_aggz);
    cudaGetSymbolAddress((void**)&cnt,    g_cnt);
    cudaGetSymbolAddress((void**)&off,    g_off);
    cudaGetSymbolAddress((void**)&cursor, g_cursor);
    cudaGetSymbolAddress((void**)&srt,    g_srt);
    cudaGetSymbolAddress((void**)&bsum,   g_bsum);
    cudaGetSymbolAddress((void**)&bpre,   g_bpre);

    const int nb = (N + 1023) / 1024;

    // 1) CSR build (multi-block scan)
    zero_i<<<(N + 255) / 256, 256>>>(cnt, N);
    count_kernel<<<(E + 255) / 256, 256>>>(dst, E, N, cnt);
    block_sum<<<nb, 1024>>>(cnt, N, bsum);
    scan_sums<<<1, 32>>>(bsum, bpre, nb);
    block_scan<<<nb, 1024>>>(cnt, bpre, off, cursor, N);
    scatter_kernel<<<(E + 255) / 256, 256>>>(src, dst, E, N, cursor, srt);

    // 2) hi/lo conversions (w2cat: Ws2 rows 0-127, Wn2 rows 128-255)
    conv_hilo<<<(N * F_IN + 255) / 256, 256>>>(x, x_hi, x_lo, N * F_IN);
    conv_hilo<<<128, 256>>>(Ws1, w_hi + 0,      w_lo + 0,      H * F_IN);
    conv_hilo<<<128, 256>>>(Wn1, w_hi + 32768,  w_lo + 32768,  H * F_IN);
    conv_hilo<<<128, 256>>>(Ws2, w_hi + 65536,  w_lo + 65536,  F_OUT * H);
    conv_hilo<<<128, 256>>>(Wn2, w_hi + 98304,  w_lo + 98304,  F_OUT * H);

    // 3) layer-1 aggregation -> a1 hi/lo (bf16)
    gather128<true><<<(N * 32 + 255) / 256, 256>>>(x, F_IN, 0, srt, off,
                                                   a1_hi, a1_lo, nullptr, N);

    // 4) GEMM1: h1 = relu(x Ws1^T + a1 Wn1^T + b1) -> h1 hi/lo, ldc=256
    {
        Seg sA{x_hi, x_lo, w_hi, w_lo};
        Seg sB{a1_hi, a1_lo, w_hi + 32768, w_lo + 32768};
        dim3 grid(H / 128, (N + 127) / 128);
        gemm3<2, 128, 1><<<grid, 256>>>(sA, sB, N, b1, nullptr, h1_hi, h1_lo, H);
    }

    // 5) GEMM2: [s2|z2] = h1 [Ws2;Wn2]^T (raw fp32), ldc=256
    {
        Seg sA{h1_hi, h1_lo, w_hi + 65536, w_lo + 65536};
        dim3 grid(2, (N + 127) / 128);
        gemm3<1, 256, 0><<<grid, 256>>>(sA, sA, N, nullptr, s2z2, nullptr,
                                        nullptr, 256);
    }

    // 6) layer-2 aggregation over z2 (cols 128..255 of s2z2) -> aggz fp32
    gather128<false><<<(N * 32 + 255) / 256, 256>>>(s2z2, 256, 128, srt, off,
                                                    nullptr, nullptr, aggz, N);

    // 7) out = relu(s2 + aggz + b2)
    add_relu<<<(N * 32 + 255) / 256, 256>>>(s2z2, aggz, b2, out, N);
}

// round 8
// speedup vs baseline: 2.5234x; 1.1462x over previous
#include <cuda_runtime.h>
#include <cuda_bf16.h>
#include <cstdint>

// ---------------- scratch (static device globals; no allocation allowed) ----
#define N_CAP   50176
#define E_CAP   1000448
#define MAXBLK  64

__device__ uint16_t g_x_hi [N_CAP * 128];
__device__ uint16_t g_x_lo [N_CAP * 128];
__device__ uint16_t g_a1_hi[N_CAP * 128];
__device__ uint16_t g_a1_lo[N_CAP * 128];
__device__ uint16_t g_h1_hi[N_CAP * 256];
__device__ uint16_t g_h1_lo[N_CAP * 256];
__device__ float    g_s2z2 [N_CAP * 256];   // [s2 | z2] fp32
__device__ uint16_t g_w_hi [131072];        // Ws1 | Wn1 | Ws2 | Wn2
__device__ uint16_t g_w_lo [131072];
__device__ int      g_cnt   [N_CAP];
__device__ int      g_off   [N_CAP + 1];
__device__ int      g_cursor[N_CAP];
__device__ int      g_srt   [E_CAP];
__device__ int      g_bsum  [MAXBLK];

// ---------------- small helpers ----------------------------------------------
__device__ __forceinline__ uint32_t smem_u32(const void* p) {
    uint32_t a;
    asm("{ .reg .u64 t; cvta.to.shared.u64 t, %1; cvt.u32.u64 %0, t; }"
        : "=r"(a) : "l"(p));
    return a;
}
__device__ __forceinline__ void hilo(float v, uint16_t& h, uint16_t& l) {
    __nv_bfloat16 hb = __float2bfloat16(v);
    __nv_bfloat16 lb = __float2bfloat16(v - __bfloat162float(hb));
    h = __bfloat16_as_ushort(hb);
    l = __bfloat16_as_ushort(lb);
}
__device__ __forceinline__ void ldsm_x4(uint32_t* r, uint32_t addr) {
    asm volatile("ldmatrix.sync.aligned.m8n8.x4.shared.b16 {%0,%1,%2,%3}, [%4];"
                 : "=r"(r[0]), "=r"(r[1]), "=r"(r[2]), "=r"(r[3]) : "r"(addr));
}
__device__ __forceinline__ void ldsm_x2(uint32_t* r, uint32_t addr) {
    asm volatile("ldmatrix.sync.aligned.m8n8.x2.shared.b16 {%0,%1}, [%2];"
                 : "=r"(r[0]), "=r"(r[1]) : "r"(addr));
}
__device__ __forceinline__ void mma_bf16(float* d, const uint32_t* a,
                                         const uint32_t* b) {
    asm volatile(
        "mma.sync.aligned.m16n8k16.row.col.f32.bf16.bf16.f32 "
        "{%0,%1,%2,%3}, {%4,%5,%6,%7}, {%8,%9}, {%0,%1,%2,%3};"
        : "+f"(d[0]), "+f"(d[1]), "+f"(d[2]), "+f"(d[3])
        : "r"(a[0]), "r"(a[1]), "r"(a[2]), "r"(a[3]), "r"(b[0]), "r"(b[1]));
}
__device__ __forceinline__ void cp16(uint32_t smem, const void* g, uint32_t sz) {
    asm volatile("cp.async.ca.shared.global [%0], [%1], 16, %2;"
                 :: "r"(smem), "l"(g), "r"(sz) : "memory");
}
#define CP_COMMIT() asm volatile("cp.async.commit_group;" ::: "memory")
#define CP_WAIT1()  asm volatile("cp.async.wait_group 1;" ::: "memory")
#define CP_WAIT0()  asm volatile("cp.async.wait_group 0;" ::: "memory")

// ---------------- CSR build ---------------------------------------------------
__global__ void zero_i(int* __restrict__ p, int n) {
    int i = blockIdx.x * blockDim.x + threadIdx.x;
    if (i < n) p[i] = 0;
}

__global__ void count_kernel(const int* __restrict__ dst, int E, int N,
                             int* __restrict__ cnt) {
    int i = blockIdx.x * blockDim.x + threadIdx.x;
    if (i >= E) return;
    int d = min(max(dst[i], 0), N - 1);
    atomicAdd(&cnt[d], 1);
}

__global__ void block_sum(const int* __restrict__ cnt, int N,
                          int* __restrict__ bsum) {
    __shared__ int sh[1024];
    int i = blockIdx.x * 1024 + threadIdx.x;
    sh[threadIdx.x] = (i < N) ? cnt[i] : 0;
    __syncthreads();
    for (int d = 512; d > 0; d >>= 1) {
        if (threadIdx.x < d) sh[threadIdx.x] += sh[threadIdx.x + d];
        __syncthreads();
    }
    if (threadIdx.x == 0) bsum[blockIdx.x] = sh[0];
}

// per-block scan; carry computed inline from bsum (nb <= 64, trivial)
__global__ void block_scan(const int* __restrict__ cnt,
                           const int* __restrict__ bsum,
                           int* __restrict__ off, int* __restrict__ cursor,
                           int N) {
    __shared__ int sh[1024];
    __shared__ int carry_s;
    int tid = threadIdx.x;
    if (tid == 0) {
        int a = 0;
        for (int i = 0; i < (int)blockIdx.x; i++) a += bsum[i];
        carry_s = a;
    }
    int i = blockIdx.x * 1024 + tid;
    int v = (i < N) ? cnt[i] : 0;
    sh[tid] = v;
    __syncthreads();
#pragma unroll
    for (int d = 1; d < 1024; d <<= 1) {
        int t = (tid >= d) ? sh[tid - d] : 0;
        __syncthreads();
        sh[tid] += t;
        __syncthreads();
    }
    int incl = sh[tid] + carry_s;
    if (i < N) {
        off[i + 1] = incl;
        cursor[i]  = incl - v;
    }
    if (blockIdx.x == 0 && tid == 0) off[0] = 0;
}

__global__ void scatter_kernel(const int* __restrict__ src,
                               const int* __restrict__ dst, int E, int N,
                               int* __restrict__ cursor, int* __restrict__ srt) {
    int i = blockIdx.x * blockDim.x + threadIdx.x;
    if (i >= E) return;
    int d = min(max(dst[i], 0), N - 1);
    int s = min(max(src[i], 0), N - 1);
    int pos = atomicAdd(&cursor[d], 1);
    srt[pos] = s;
}

// ---------------- fp32 -> bf16 hi/lo conversions ------------------------------
__global__ void conv_hilo(const float* __restrict__ s, uint16_t* __restrict__ hi,
                          uint16_t* __restrict__ lo, int n) {
    int i = blockIdx.x * blockDim.x + threadIdx.x;
    if (i < n) hilo(s[i], hi[i], lo[i]);
}

// all 4 weight matrices in one launch (each 32768 elements)
__global__ void conv_w(const float* __restrict__ w0, const float* __restrict__ w1,
                       const float* __restrict__ w2, const float* __restrict__ w3,
                       uint16_t* __restrict__ hi, uint16_t* __restrict__ lo) {
    int i = blockIdx.x * blockDim.x + threadIdx.x;
    if (i >= 131072) return;
    int which = i >> 15, idx = i & 32767;
    const float* w = (which == 0) ? w0 : (which == 1) ? w1
                   : (which == 2) ? w2 : w3;
    hilo(w[idx], hi[i], lo[i]);
}

// ---------------- gather aggregation (layer 1): x fp32 -> a1 hi/lo -------------
__global__ void gather1(const float* __restrict__ x,
                        const int* __restrict__ srt,
                        const int* __restrict__ off,
                        uint16_t* __restrict__ hi, uint16_t* __restrict__ lo,
                        int N) {
    int warp = (blockIdx.x * blockDim.x + threadIdx.x) >> 5;
    int lane = threadIdx.x & 31;
    if (warp >= N) return;
    int s0 = off[warp], s1 = off[warp + 1];

    float4 acc = make_float4(0.f, 0.f, 0.f, 0.f);
    int e = s0;
    for (; e + 1 < s1; e += 2) {
        int sA = srt[e], sB = srt[e + 1];
        float4 a = *reinterpret_cast<const float4*>(x + (size_t)sA * 128 + lane * 4);
        float4 b = *reinterpret_cast<const float4*>(x + (size_t)sB * 128 + lane * 4);
        acc.x += a.x + b.x; acc.y += a.y + b.y;
        acc.z += a.z + b.z; acc.w += a.w + b.w;
    }
    if (e < s1) {
        int sA = srt[e];
        float4 a = *reinterpret_cast<const float4*>(x + (size_t)sA * 128 + lane * 4);
        acc.x += a.x; acc.y += a.y; acc.z += a.z; acc.w += a.w;
    }

    float r = (s1 > s0) ? 1.0f / (float)(s1 - s0) : 0.0f;
    acc.x *= r; acc.y *= r; acc.z *= r; acc.w *= r;

    uint16_t h0, l0, h1v, l1, h2, l2, h3, l3;
    hilo(acc.x, h0, l0); hilo(acc.y, h1v, l1);
    hilo(acc.z, h2, l2); hilo(acc.w, h3, l3);
    size_t base = (size_t)warp * 128 + lane * 4;
    *reinterpret_cast<uint2*>(hi + base) =
        make_uint2((uint32_t)h0 | ((uint32_t)h1v << 16),
                   (uint32_t)h2 | ((uint32_t)h3 << 16));
    *reinterpret_cast<uint2*>(lo + base) =
        make_uint2((uint32_t)l0 | ((uint32_t)l1 << 16),
                   (uint32_t)l2 | ((uint32_t)l3 << 16));
}

// ---------------- fused layer-2 finish: out = relu(s2 + agg(z2) + b2) ---------
__global__ void gather_out(const float* __restrict__ s2z2,
                           const int* __restrict__ srt,
                           const int* __restrict__ off,
                           const float* __restrict__ bias,
                           float* __restrict__ out, int N) {
    int warp = (blockIdx.x * blockDim.x + threadIdx.x) >> 5;
    int lane = threadIdx.x & 31;
    if (warp >= N) return;
    int s0 = off[warp], s1 = off[warp + 1];

    float4 acc = make_float4(0.f, 0.f, 0.f, 0.f);
    int e = s0;
    for (; e + 1 < s1; e += 2) {
        int sA = srt[e], sB = srt[e + 1];
        float4 a = *reinterpret_cast<const float4*>(
            s2z2 + (size_t)sA * 256 + 128 + lane * 4);
        float4 b = *reinterpret_cast<const float4*>(
            s2z2 + (size_t)sB * 256 + 128 + lane * 4);
        acc.x += a.x + b.x; acc.y += a.y + b.y;
        acc.z += a.z + b.z; acc.w += a.w + b.w;
    }
    if (e < s1) {
        int sA = srt[e];
        float4 a = *reinterpret_cast<const float4*>(
            s2z2 + (size_t)sA * 256 + 128 + lane * 4);
        acc.x += a.x; acc.y += a.y; acc.z += a.z; acc.w += a.w;
    }

    float r = (s1 > s0) ? 1.0f / (float)(s1 - s0) : 0.0f;
    float4 s = *reinterpret_cast<const float4*>(s2z2 + (size_t)warp * 256 + lane * 4);
    float4 b = *reinterpret_cast<const float4*>(bias + lane * 4);
    float4 o;
    o.x = fmaxf(s.x + acc.x * r + b.x, 0.f);
    o.y = fmaxf(s.y + acc.y * r + b.y, 0.f);
    o.z = fmaxf(s.z + acc.z * r + b.z, 0.f);
    o.w = fmaxf(s.w + acc.w * r + b.w, 0.f);
    *reinterpret_cast<float4*>(out + (size_t)warp * 128 + lane * 4) = o;
}

// ---------------- bf16x3 GEMM, cp.async double-buffered ------------------------
struct Seg { const uint16_t *ahi, *alo, *bhi, *blo; };

// SMEM stage layout: AsH | AsL | BsH | BsL, each 128*40 bf16 = 10240 B
#define T_BYTES 10240
#define STAGE   (4 * T_BYTES)

template <int NSEG, int SEGD, int OUTMODE>   // OUTMODE 0: raw fp32; 1: bias+relu->hilo
__global__ void __launch_bounds__(256)
gemm3(Seg s0, Seg s1, int M, const float* __restrict__ bias,
      float* __restrict__ C, uint16_t* __restrict__ Chi,
      uint16_t* __restrict__ Clo, int ldc) {
    extern __shared__ char dsm[];
    uint32_t sb = smem_u32(dsm);

    int tid = threadIdx.x;
    int wid = tid >> 5;
    int lane = tid & 31;
    int rowBase = blockIdx.y * 128;
    int colBase = blockIdx.x * 128;
    int warp_m = (wid & 3) * 32;
    int warp_n = (wid >> 2) * 64;

    float acc[2][8][4] = {};

    constexpr int ITER_PER_SEG = SEGD / 32;
    constexpr int NITER = NSEG * ITER_PER_SEG;

    auto load_stage = [&](int it, int buf) {
        Seg sg = (NSEG == 1 || it < ITER_PER_SEG) ? s0 : s1;
        int kin = (it % ITER_PER_SEG) * 32;
        uint32_t sbase = sb + buf * STAGE;
#pragma unroll
        for (int h = 0; h < 2; h++) {
            int f  = tid + h * 256;
            int r  = f >> 2;
            int c8 = (f & 3) * 8;
            int gm = rowBase + r;
            uint32_t asz = (gm < M) ? 16u : 0u;
            int gmc = min(gm, M - 1);
            uint32_t so = sbase + (uint32_t)(r * 40 + c8) * 2;
            size_t ao = (size_t)gmc * SEGD + kin + c8;
            cp16(so,               sg.ahi + ao, asz);
            cp16(so + T_BYTES,     sg.alo + ao, asz);
            size_t bo = (size_t)(colBase + r) * SEGD + kin + c8;
            cp16(so + 2 * T_BYTES, sg.bhi + bo, 16);
            cp16(so + 3 * T_BYTES, sg.blo + bo, 16);
        }
        CP_COMMIT();
    };

    load_stage(0, 0);

    for (int it = 0; it < NITER; it++) {
        if (it + 1 < NITER) {
            load_stage(it + 1, (it + 1) & 1);
            CP_WAIT1();
        } else {
            CP_WAIT0();
        }
        __syncthreads();

        uint32_t sbase = sb + (it & 1) * STAGE;
        uint32_t asH = sbase, asL = sbase + T_BYTES;
        uint32_t bsH = sbase + 2 * T_BYTES, bsL = sbase + 3 * T_BYTES;

#pragma unroll
        for (int ks = 0; ks < 32; ks += 16) {
            uint32_t bH[8][2], bL[8][2];
#pragma unroll
            for (int nt = 0; nt < 8; nt++) {
                uint32_t roff = (uint32_t)((warp_n + nt * 8 + (lane & 7)) * 40 +
                                           ks + ((lane >> 3) & 1) * 8) * 2;
                ldsm_x2(bH[nt], bsH + roff);
                ldsm_x2(bL[nt], bsL + roff);
            }
#pragma unroll
            for (int mt = 0; mt < 2; mt++) {
                uint32_t aH[4], aL[4];
                uint32_t roff = (uint32_t)((warp_m + mt * 16 + (lane & 15)) * 40 +
                                           ks + (lane >> 4) * 8) * 2;
                ldsm_x4(aH, asH + roff);
                ldsm_x4(aL, asL + roff);
#pragma unroll
                for (int nt = 0; nt < 8; nt++) {
                    mma_bf16(acc[mt][nt], aH, bH[nt]);
                    mma_bf16(acc[mt][nt], aH, bL[nt]);
                    mma_bf16(acc[mt][nt], aL, bH[nt]);
                }
            }
        }
        __syncthreads();
    }

    // epilogue
#pragma unroll
    for (int mt = 0; mt < 2; mt++) {
        int gm0 = rowBase + warp_m + mt * 16 + (lane >> 2);
#pragma unroll
        for (int nt = 0; nt < 8; nt++) {
            int n = colBase + warp_n + nt * 8 + (lane & 3) * 2;
#pragma unroll
            for (int half = 0; half < 2; half++) {
                int gm = gm0 + half * 8;
                if (gm >= M) continue;
                float v0 = acc[mt][nt][half * 2 + 0];
                float v1 = acc[mt][nt][half * 2 + 1];
                if (OUTMODE == 1) {
                    v0 = fmaxf(v0 + bias[n], 0.f);
                    v1 = fmaxf(v1 + bias[n + 1], 0.f);
                    uint16_t h0, l0, h1v, l1;
                    hilo(v0, h0, l0); hilo(v1, h1v, l1);
                    *reinterpret_cast<uint32_t*>(Chi + (size_t)gm * ldc + n) =
                        (uint32_t)h0 | ((uint32_t)h1v << 16);
                    *reinterpret_cast<uint32_t*>(Clo + (size_t)gm * ldc + n) =
                        (uint32_t)l0 | ((uint32_t)l1 << 16);
                } else {
                    *reinterpret_cast<float2*>(C + (size_t)gm * ldc + n) =
                        make_float2(v0, v1);
                }
            }
        }
    }
}

// ---------------- launch -------------------------------------------------------
extern "C" void kernel_launch(void* const* d_in, const int* in_sizes, int n_in,
                              void* d_out, int out_size) {
    const float* x   = (const float*)d_in[0];
    const int*   ei  = (const int*)d_in[1];
    const float* Ws1 = (const float*)d_in[2];
    const float* Wn1 = (const float*)d_in[3];
    const float* b1  = (const float*)d_in[4];
    const float* Ws2 = (const float*)d_in[5];
    const float* Wn2 = (const float*)d_in[6];
    const float* b2  = (const float*)d_in[7];
    float*       out = (float*)d_out;

    const int H     = in_sizes[4];             // 256
    const int F_IN  = in_sizes[2] / H;         // 128
    const int N     = in_sizes[0] / F_IN;      // 50000
    const int E     = in_sizes[1] / 2;         // 800000
    const int F_OUT = in_sizes[7];             // 128

    const int* src = ei;
    const int* dst = ei + E;

    uint16_t *x_hi, *x_lo, *a1_hi, *a1_lo, *h1_hi, *h1_lo, *w_hi, *w_lo;
    float *s2z2;
    int *cnt, *off, *cursor, *srt, *bsum;
    cudaGetSymbolAddress((void**)&x_hi,  g_x_hi);
    cudaGetSymbolAddress((void**)&x_lo,  g_x_lo);
    cudaGetSymbolAddress((void**)&a1_hi, g_a1_hi);
    cudaGetSymbolAddress((void**)&a1_lo, g_a1_lo);
    cudaGetSymbolAddress((void**)&h1_hi, g_h1_hi);
    cudaGetSymbolAddress((void**)&h1_lo, g_h1_lo);
    cudaGetSymbolAddress((void**)&w_hi,  g_w_hi);
    cudaGetSymbolAddress((void**)&w_lo,  g_w_lo);
    cudaGetSymbolAddress((void**)&s2z2,  g_s2z2);
    cudaGetSymbolAddress((void**)&cnt,    g_cnt);
    cudaGetSymbolAddress((void**)&off,    g_off);
    cudaGetSymbolAddress((void**)&cursor, g_cursor);
    cudaGetSymbolAddress((void**)&srt,    g_srt);
    cudaGetSymbolAddress((void**)&bsum,   g_bsum);

    const int nb = (N + 1023) / 1024;
    const int DSMEM = 2 * STAGE;   // 81920

    cudaFuncSetAttribute(gemm3<2, 128, 1>,
                         cudaFuncAttributeMaxDynamicSharedMemorySize, DSMEM);
    cudaFuncSetAttribute(gemm3<1, 256, 0>,
                         cudaFuncAttributeMaxDynamicSharedMemorySize, DSMEM);

    // 1) CSR build
    zero_i<<<(N + 255) / 256, 256>>>(cnt, N);
    count_kernel<<<(E + 255) / 256, 256>>>(dst, E, N, cnt);
    block_sum<<<nb, 1024>>>(cnt, N, bsum);
    block_scan<<<nb, 1024>>>(cnt, bsum, off, cursor, N);
    scatter_kernel<<<(E + 255) / 256, 256>>>(src, dst, E, N, cursor, srt);

    // 2) hi/lo conversions
    conv_hilo<<<(N * F_IN + 255) / 256, 256>>>(x, x_hi, x_lo, N * F_IN);
    conv_w<<<512, 256>>>(Ws1, Wn1, Ws2, Wn2, w_hi, w_lo);

    // 3) layer-1 aggregation -> a1 hi/lo
    gather1<<<(N * 32 + 255) / 256, 256>>>(x, srt, off, a1_hi, a1_lo, N);

    // 4) GEMM1: h1 = relu(x Ws1^T + a1 Wn1^T + b1) -> h1 hi/lo (ldc = 256)
    {
        Seg sA{x_hi, x_lo, w_hi, w_lo};
        Seg sB{a1_hi, a1_lo, w_hi + 32768, w_lo + 32768};
        dim3 grid(H / 128, (N + 127) / 128);
        gemm3<2, 128, 1><<<grid, 256, DSMEM>>>(sA, sB, N, b1, nullptr,
                                               h1_hi, h1_lo, H);
    }

    // 5) GEMM2: [s2|z2] = h1 [Ws2;Wn2]^T (raw fp32, ldc = 256)
    {
        Seg sA{h1_hi, h1_lo, w_hi + 65536, w_lo + 65536};
        dim3 grid(2, (N + 127) / 128);
        gemm3<1, 256, 0><<<grid, 256, DSMEM>>>(sA, sA, N, nullptr, s2z2,
                                               nullptr, nullptr, 256);
    }

    // 6) fused: out = relu(s2 + agg(z2) + b2)
    gather_out<<<(N * 32 + 255) / 256, 256>>>(s2z2, srt, off, b2, out, N);
}

// round 9
// speedup vs baseline: 2.5512x; 1.0110x over previous
#include <cuda_runtime.h>
#include <cuda_bf16.h>
#include <cstdint>

// ---------------- scratch (static device globals; no allocation allowed) ----
#define N_CAP   50176
#define E_CAP   1000448
#define MAXBLK  64

__device__ uint16_t g_x_hi [N_CAP * 128];
__device__ uint16_t g_x_lo [N_CAP * 128];
__device__ uint16_t g_a1_hi[N_CAP * 128];
__device__ uint16_t g_a1_lo[N_CAP * 128];
__device__ uint16_t g_h1_hi[N_CAP * 256];
__device__ uint16_t g_h1_lo[N_CAP * 256];
__device__ float    g_s2z2 [N_CAP * 256];   // [s2 | z2] fp32
__device__ uint16_t g_w_hi [131072];        // Ws1 | Wn1 | Ws2 | Wn2
__device__ uint16_t g_w_lo [131072];
__device__ int      g_cnt   [N_CAP];
__device__ int      g_off   [N_CAP + 1];
__device__ int      g_cursor[N_CAP];
__device__ int      g_srt   [E_CAP];
__device__ int      g_bsum  [MAXBLK];

// ---------------- small helpers ----------------------------------------------
__device__ __forceinline__ uint32_t smem_u32(const void* p) {
    uint32_t a;
    asm("{ .reg .u64 t; cvta.to.shared.u64 t, %1; cvt.u32.u64 %0, t; }"
        : "=r"(a) : "l"(p));
    return a;
}
__device__ __forceinline__ void hilo(float v, uint16_t& h, uint16_t& l) {
    __nv_bfloat16 hb = __float2bfloat16(v);
    __nv_bfloat16 lb = __float2bfloat16(v - __bfloat162float(hb));
    h = __bfloat16_as_ushort(hb);
    l = __bfloat16_as_ushort(lb);
}
__device__ __forceinline__ void ldsm_x4(uint32_t* r, uint32_t addr) {
    asm volatile("ldmatrix.sync.aligned.m8n8.x4.shared.b16 {%0,%1,%2,%3}, [%4];"
                 : "=r"(r[0]), "=r"(r[1]), "=r"(r[2]), "=r"(r[3]) : "r"(addr));
}
__device__ __forceinline__ void ldsm_x2(uint32_t* r, uint32_t addr) {
    asm volatile("ldmatrix.sync.aligned.m8n8.x2.shared.b16 {%0,%1}, [%2];"
                 : "=r"(r[0]), "=r"(r[1]) : "r"(addr));
}
__device__ __forceinline__ void mma_bf16(float* d, const uint32_t* a,
                                         const uint32_t* b) {
    asm volatile(
        "mma.sync.aligned.m16n8k16.row.col.f32.bf16.bf16.f32 "
        "{%0,%1,%2,%3}, {%4,%5,%6,%7}, {%8,%9}, {%0,%1,%2,%3};"
        : "+f"(d[0]), "+f"(d[1]), "+f"(d[2]), "+f"(d[3])
        : "r"(a[0]), "r"(a[1]), "r"(a[2]), "r"(a[3]), "r"(b[0]), "r"(b[1]));
}
__device__ __forceinline__ void cp16(uint32_t smem, const void* g, uint32_t sz) {
    asm volatile("cp.async.ca.shared.global [%0], [%1], 16, %2;"
                 :: "r"(smem), "l"(g), "r"(sz) : "memory");
}
#define CP_COMMIT() asm volatile("cp.async.commit_group;" ::: "memory")
#define CP_WAIT1()  asm volatile("cp.async.wait_group 1;" ::: "memory")
#define CP_WAIT0()  asm volatile("cp.async.wait_group 0;" ::: "memory")

// ---------------- CSR build ---------------------------------------------------
__global__ void zero_i(int* __restrict__ p, int n) {
    int i = blockIdx.x * blockDim.x + threadIdx.x;
    if (i < n) p[i] = 0;
}

// 2 edges per thread
__global__ void count_kernel(const int* __restrict__ dst, int E, int N,
                             int* __restrict__ cnt) {
    int i = (blockIdx.x * blockDim.x + threadIdx.x) * 2;
    if (i + 1 < E) {
        int2 d2 = *reinterpret_cast<const int2*>(dst + i);
        atomicAdd(&cnt[min(max(d2.x, 0), N - 1)], 1);
        atomicAdd(&cnt[min(max(d2.y, 0), N - 1)], 1);
    } else if (i < E) {
        atomicAdd(&cnt[min(max(dst[i], 0), N - 1)], 1);
    }
}

__global__ void block_sum(const int* __restrict__ cnt, int N,
                          int* __restrict__ bsum) {
    __shared__ int sh[1024];
    int i = blockIdx.x * 1024 + threadIdx.x;
    sh[threadIdx.x] = (i < N) ? cnt[i] : 0;
    __syncthreads();
    for (int d = 512; d > 0; d >>= 1) {
        if (threadIdx.x < d) sh[threadIdx.x] += sh[threadIdx.x + d];
        __syncthreads();
    }
    if (threadIdx.x == 0) bsum[blockIdx.x] = sh[0];
}

__global__ void block_scan(const int* __restrict__ cnt,
                           const int* __restrict__ bsum,
                           int* __restrict__ off, int* __restrict__ cursor,
                           int N) {
    __shared__ int sh[1024];
    __shared__ int carry_s;
    int tid = threadIdx.x;
    if (tid == 0) {
        int a = 0;
        for (int i = 0; i < (int)blockIdx.x; i++) a += bsum[i];
        carry_s = a;
    }
    int i = blockIdx.x * 1024 + tid;
    int v = (i < N) ? cnt[i] : 0;
    sh[tid] = v;
    __syncthreads();
#pragma unroll
    for (int d = 1; d < 1024; d <<= 1) {
        int t = (tid >= d) ? sh[tid - d] : 0;
        __syncthreads();
        sh[tid] += t;
        __syncthreads();
    }
    int incl = sh[tid] + carry_s;
    if (i < N) {
        off[i + 1] = incl;
        cursor[i]  = incl - v;
    }
    if (blockIdx.x == 0 && tid == 0) off[0] = 0;
}

// 2 edges per thread
__global__ void scatter_kernel(const int* __restrict__ src,
                               const int* __restrict__ dst, int E, int N,
                               int* __restrict__ cursor, int* __restrict__ srt) {
    int i = (blockIdx.x * blockDim.x + threadIdx.x) * 2;
    if (i + 1 < E) {
        int2 s2 = *reinterpret_cast<const int2*>(src + i);
        int2 d2 = *reinterpret_cast<const int2*>(dst + i);
        int p0 = atomicAdd(&cursor[min(max(d2.x, 0), N - 1)], 1);
        srt[p0] = min(max(s2.x, 0), N - 1);
        int p1 = atomicAdd(&cursor[min(max(d2.y, 0), N - 1)], 1);
        srt[p1] = min(max(s2.y, 0), N - 1);
    } else if (i < E) {
        int p0 = atomicAdd(&cursor[min(max(dst[i], 0), N - 1)], 1);
        srt[p0] = min(max(src[i], 0), N - 1);
    }
}

// ---------------- fp32 -> bf16 hi/lo conversions ------------------------------
__global__ void conv_hilo(const float* __restrict__ s, uint16_t* __restrict__ hi,
                          uint16_t* __restrict__ lo, int n) {
    int i = blockIdx.x * blockDim.x + threadIdx.x;
    if (i < n) hilo(s[i], hi[i], lo[i]);
}

__global__ void conv_w(const float* __restrict__ w0, const float* __restrict__ w1,
                       const float* __restrict__ w2, const float* __restrict__ w3,
                       uint16_t* __restrict__ hi, uint16_t* __restrict__ lo) {
    int i = blockIdx.x * blockDim.x + threadIdx.x;
    if (i >= 131072) return;
    int which = i >> 15, idx = i & 32767;
    const float* w = (which == 0) ? w0 : (which == 1) ? w1
                   : (which == 2) ? w2 : w3;
    hilo(w[idx], hi[i], lo[i]);
}

// ---------------- gather aggregation (layer 1): x fp32 -> a1 hi/lo -------------
__global__ void gather1(const float* __restrict__ x,
                        const int* __restrict__ srt,
                        const int* __restrict__ off,
                        uint16_t* __restrict__ hi, uint16_t* __restrict__ lo,
                        int N) {
    int warp = (blockIdx.x * blockDim.x + threadIdx.x) >> 5;
    int lane = threadIdx.x & 31;
    if (warp >= N) return;
    int s0 = off[warp], s1 = off[warp + 1];

    float4 acc = make_float4(0.f, 0.f, 0.f, 0.f);
    int e = s0;
    for (; e + 1 < s1; e += 2) {
        int sA = srt[e], sB = srt[e + 1];
        float4 a = *reinterpret_cast<const float4*>(x + (size_t)sA * 128 + lane * 4);
        float4 b = *reinterpret_cast<const float4*>(x + (size_t)sB * 128 + lane * 4);
        acc.x += a.x + b.x; acc.y += a.y + b.y;
        acc.z += a.z + b.z; acc.w += a.w + b.w;
    }
    if (e < s1) {
        int sA = srt[e];
        float4 a = *reinterpret_cast<const float4*>(x + (size_t)sA * 128 + lane * 4);
        acc.x += a.x; acc.y += a.y; acc.z += a.z; acc.w += a.w;
    }

    float r = (s1 > s0) ? 1.0f / (float)(s1 - s0) : 0.0f;
    acc.x *= r; acc.y *= r; acc.z *= r; acc.w *= r;

    uint16_t h0, l0, h1v, l1, h2, l2, h3, l3;
    hilo(acc.x, h0, l0); hilo(acc.y, h1v, l1);
    hilo(acc.z, h2, l2); hilo(acc.w, h3, l3);
    size_t base = (size_t)warp * 128 + lane * 4;
    *reinterpret_cast<uint2*>(hi + base) =
        make_uint2((uint32_t)h0 | ((uint32_t)h1v << 16),
                   (uint32_t)h2 | ((uint32_t)h3 << 16));
    *reinterpret_cast<uint2*>(lo + base) =
        make_uint2((uint32_t)l0 | ((uint32_t)l1 << 16),
                   (uint32_t)l2 | ((uint32_t)l3 << 16));
}

// ---------------- fused layer-2 finish: out = relu(s2 + agg(z2) + b2) ---------
__global__ void gather_out(const float* __restrict__ s2z2,
                           const int* __restrict__ srt,
                           const int* __restrict__ off,
                           const float* __restrict__ bias,
                           float* __restrict__ out, int N) {
    int warp = (blockIdx.x * blockDim.x + threadIdx.x) >> 5;
    int lane = threadIdx.x & 31;
    if (warp >= N) return;
    int s0 = off[warp], s1 = off[warp + 1];

    float4 acc = make_float4(0.f, 0.f, 0.f, 0.f);
    int e = s0;
    for (; e + 1 < s1; e += 2) {
        int sA = srt[e], sB = srt[e + 1];
        float4 a = *reinterpret_cast<const float4*>(
            s2z2 + (size_t)sA * 256 + 128 + lane * 4);
        float4 b = *reinterpret_cast<const float4*>(
            s2z2 + (size_t)sB * 256 + 128 + lane * 4);
        acc.x += a.x + b.x; acc.y += a.y + b.y;
        acc.z += a.z + b.z; acc.w += a.w + b.w;
    }
    if (e < s1) {
        int sA = srt[e];
        float4 a = *reinterpret_cast<const float4*>(
            s2z2 + (size_t)sA * 256 + 128 + lane * 4);
        acc.x += a.x; acc.y += a.y; acc.z += a.z; acc.w += a.w;
    }

    float r = (s1 > s0) ? 1.0f / (float)(s1 - s0) : 0.0f;
    float4 s = *reinterpret_cast<const float4*>(s2z2 + (size_t)warp * 256 + lane * 4);
    float4 b = *reinterpret_cast<const float4*>(bias + lane * 4);
    float4 o;
    o.x = fmaxf(s.x + acc.x * r + b.x, 0.f);
    o.y = fmaxf(s.y + acc.y * r + b.y, 0.f);
    o.z = fmaxf(s.z + acc.z * r + b.z, 0.f);
    o.w = fmaxf(s.w + acc.w * r + b.w, 0.f);
    *reinterpret_cast<float4*>(out + (size_t)warp * 128 + lane * 4) = o;
}

// ---------------- bf16x3 GEMM, cp.async double-buffered, occ 2 ----------------
struct Seg { const uint16_t *ahi, *alo, *bhi, *blo; };

#define T_BYTES 10240
#define STAGE   (4 * T_BYTES)

template <int NSEG, int SEGD, int OUTMODE>   // OUTMODE 0: raw fp32; 1: bias+relu->hilo
__global__ void __launch_bounds__(256, 2)
gemm3(Seg s0, Seg s1, int M, const float* __restrict__ bias,
      float* __restrict__ C, uint16_t* __restrict__ Chi,
      uint16_t* __restrict__ Clo, int ldc) {
    extern __shared__ char dsm[];
    uint32_t sb = smem_u32(dsm);

    int tid = threadIdx.x;
    int wid = tid >> 5;
    int lane = tid & 31;
    int rowBase = blockIdx.y * 128;
    int colBase = blockIdx.x * 128;
    int warp_m = (wid & 3) * 32;
    int warp_n = (wid >> 2) * 64;

    float acc[2][8][4] = {};

    constexpr int ITER_PER_SEG = SEGD / 32;
    constexpr int NITER = NSEG * ITER_PER_SEG;

    auto load_stage = [&](int it, int buf) {
        Seg sg = (NSEG == 1 || it < ITER_PER_SEG) ? s0 : s1;
        int kin = (it % ITER_PER_SEG) * 32;
        uint32_t sbase = sb + buf * STAGE;
#pragma unroll
        for (int h = 0; h < 2; h++) {
            int f  = tid + h * 256;
            int r  = f >> 2;
            int c8 = (f & 3) * 8;
            int gm = rowBase + r;
            uint32_t asz = (gm < M) ? 16u : 0u;
            int gmc = min(gm, M - 1);
            uint32_t so = sbase + (uint32_t)(r * 40 + c8) * 2;
            size_t ao = (size_t)gmc * SEGD + kin + c8;
            cp16(so,               sg.ahi + ao, asz);
            cp16(so + T_BYTES,     sg.alo + ao, asz);
            size_t bo = (size_t)(colBase + r) * SEGD + kin + c8;
            cp16(so + 2 * T_BYTES, sg.bhi + bo, 16);
            cp16(so + 3 * T_BYTES, sg.blo + bo, 16);
        }
        CP_COMMIT();
    };

    load_stage(0, 0);

    for (int it = 0; it < NITER; it++) {
        if (it + 1 < NITER) {
            load_stage(it + 1, (it + 1) & 1);
            CP_WAIT1();
        } else {
            CP_WAIT0();
        }
        __syncthreads();

        uint32_t sbase = sb + (it & 1) * STAGE;
        uint32_t asH = sbase, asL = sbase + T_BYTES;
        uint32_t bsH = sbase + 2 * T_BYTES, bsL = sbase + 3 * T_BYTES;

#pragma unroll
        for (int ks = 0; ks < 32; ks += 16) {
            uint32_t bH[8][2], bL[8][2];
#pragma unroll
            for (int nt = 0; nt < 8; nt++) {
                uint32_t roff = (uint32_t)((warp_n + nt * 8 + (lane & 7)) * 40 +
                                           ks + ((lane >> 3) & 1) * 8) * 2;
                ldsm_x2(bH[nt], bsH + roff);
                ldsm_x2(bL[nt], bsL + roff);
            }
#pragma unroll
            for (int mt = 0; mt < 2; mt++) {
                uint32_t aH[4], aL[4];
                uint32_t roff = (uint32_t)((warp_m + mt * 16 + (lane & 15)) * 40 +
                                           ks + (lane >> 4) * 8) * 2;
                ldsm_x4(aH, asH + roff);
                ldsm_x4(aL, asL + roff);
#pragma unroll
                for (int nt = 0; nt < 8; nt++) {
                    mma_bf16(acc[mt][nt], aH, bH[nt]);
                    mma_bf16(acc[mt][nt], aH, bL[nt]);
                    mma_bf16(acc[mt][nt], aL, bH[nt]);
                }
            }
        }
        __syncthreads();
    }

    // epilogue
#pragma unroll
    for (int mt = 0; mt < 2; mt++) {
        int gm0 = rowBase + warp_m + mt * 16 + (lane >> 2);
#pragma unroll
        for (int nt = 0; nt < 8; nt++) {
            int n = colBase + warp_n + nt * 8 + (lane & 3) * 2;
#pragma unroll
            for (int half = 0; half < 2; half++) {
                int gm = gm0 + half * 8;
                if (gm >= M) continue;
                float v0 = acc[mt][nt][half * 2 + 0];
                float v1 = acc[mt][nt][half * 2 + 1];
                if (OUTMODE == 1) {
                    v0 = fmaxf(v0 + bias[n], 0.f);
                    v1 = fmaxf(v1 + bias[n + 1], 0.f);
                    uint16_t h0, l0, h1v, l1;
                    hilo(v0, h0, l0); hilo(v1, h1v, l1);
                    *reinterpret_cast<uint32_t*>(Chi + (size_t)gm * ldc + n) =
                        (uint32_t)h0 | ((uint32_t)h1v << 16);
                    *reinterpret_cast<uint32_t*>(Clo + (size_t)gm * ldc + n) =
                        (uint32_t)l0 | ((uint32_t)l1 << 16);
                } else {
                    *reinterpret_cast<float2*>(C + (size_t)gm * ldc + n) =
                        make_float2(v0, v1);
                }
            }
        }
    }
}

// ---------------- launch -------------------------------------------------------
extern "C" void kernel_launch(void* const* d_in, const int* in_sizes, int n_in,
                              void* d_out, int out_size) {
    const float* x   = (const float*)d_in[0];
    const int*   ei  = (const int*)d_in[1];
    const float* Ws1 = (const float*)d_in[2];
    const float* Wn1 = (const float*)d_in[3];
    const float* b1  = (const float*)d_in[4];
    const float* Ws2 = (const float*)d_in[5];
    const float* Wn2 = (const float*)d_in[6];
    const float* b2  = (const float*)d_in[7];
    float*       out = (float*)d_out;

    const int H     = in_sizes[4];             // 256
    const int F_IN  = in_sizes[2] / H;         // 128
    const int N     = in_sizes[0] / F_IN;      // 50000
    const int E     = in_sizes[1] / 2;         // 800000
    const int F_OUT = in_sizes[7];             // 128

    const int* src = ei;
    const int* dst = ei + E;

    uint16_t *x_hi, *x_lo, *a1_hi, *a1_lo, *h1_hi, *h1_lo, *w_hi, *w_lo;
    float *s2z2;
    int *cnt, *off, *cursor, *srt, *bsum;
    cudaGetSymbolAddress((void**)&x_hi,  g_x_hi);
    cudaGetSymbolAddress((void**)&x_lo,  g_x_lo);
    cudaGetSymbolAddress((void**)&a1_hi, g_a1_hi);
    cudaGetSymbolAddress((void**)&a1_lo, g_a1_lo);
    cudaGetSymbolAddress((void**)&h1_hi, g_h1_hi);
    cudaGetSymbolAddress((void**)&h1_lo, g_h1_lo);
    cudaGetSymbolAddress((void**)&w_hi,  g_w_hi);
    cudaGetSymbolAddress((void**)&w_lo,  g_w_lo);
    cudaGetSymbolAddress((void**)&s2z2,  g_s2z2);
    cudaGetSymbolAddress((void**)&cnt,    g_cnt);
    cudaGetSymbolAddress((void**)&off,    g_off);
    cudaGetSymbolAddress((void**)&cursor, g_cursor);
    cudaGetSymbolAddress((void**)&srt,    g_srt);
    cudaGetSymbolAddress((void**)&bsum,   g_bsum);

    const int nb = (N + 1023) / 1024;
    const int DSMEM = 2 * STAGE;   // 81920

    cudaFuncSetAttribute(gemm3<2, 128, 1>,
                         cudaFuncAttributeMaxDynamicSharedMemorySize, DSMEM);
    cudaFuncSetAttribute(gemm3<1, 256, 0>,
                         cudaFuncAttributeMaxDynamicSharedMemorySize, DSMEM);

    // 1) CSR build
    zero_i<<<(N + 255) / 256, 256>>>(cnt, N);
    count_kernel<<<(E / 2 + 255) / 256, 256>>>(dst, E, N, cnt);
    block_sum<<<nb, 1024>>>(cnt, N, bsum);
    block_scan<<<nb, 1024>>>(cnt, bsum, off, cursor, N);
    scatter_kernel<<<(E / 2 + 255) / 256, 256>>>(src, dst, E, N, cursor, srt);

    // 2) hi/lo conversions
    conv_hilo<<<(N * F_IN + 255) / 256, 256>>>(x, x_hi, x_lo, N * F_IN);
    conv_w<<<512, 256>>>(Ws1, Wn1, Ws2, Wn2, w_hi, w_lo);

    // 3) layer-1 aggregation -> a1 hi/lo
    gather1<<<(N * 32 + 255) / 256, 256>>>(x, srt, off, a1_hi, a1_lo, N);

    // 4) GEMM1: h1 = relu(x Ws1^T + a1 Wn1^T + b1) -> h1 hi/lo (ldc = 256)
    {
        Seg sA{x_hi, x_lo, w_hi, w_lo};
        Seg sB{a1_hi, a1_lo, w_hi + 32768, w_lo + 32768};
        dim3 grid(H / 128, (N + 127) / 128);
        gemm3<2, 128, 1><<<grid, 256, DSMEM>>>(sA, sB, N, b1, nullptr,
                                               h1_hi, h1_lo, H);
    }

    // 5) GEMM2: [s2|z2] = h1 [Ws2;Wn2]^T (raw fp32, ldc = 256)
    {
        Seg sA{h1_hi, h1_lo, w_hi + 65536, w_lo + 65536};
        dim3 grid(2, (N + 127) / 128);
        gemm3<1, 256, 0><<<grid, 256, DSMEM>>>(sA, sA, N, nullptr, s2z2,
                                               nullptr, nullptr, 256);
    }

    // 6) fused: out = relu(s2 + agg(z2) + b2)
    gather_out<<<(N * 32 + 255) / 256, 256>>>(s2z2, srt, off, b2, out, N);
}